// round 1
// baseline (speedup 1.0000x reference)
#include <cuda_runtime.h>
#include <cuda_bf16.h>
#include <cstdint>
#include <cstddef>

// ---------------------------------------------------------------------------
// Problem constants
// ---------------------------------------------------------------------------
#define Dm    512
#define Bn    8
#define Hh    64
#define Ww    64
#define Nn    (Hh*Ww)      // 4096
#define Qq    200
#define C2    256
#define NH    8
#define NH2   4
#define HD    64
#define L1    256          // 16x16
#define L2    1024         // 32x32
#define M1    (Bn*L1)      // 2048
#define M2    (Bn*L2)      // 8192
#define K1    (Dm*16)      // 8192 (4x4 patch)
#define K2    (Dm*4)       // 2048 (2x2 patch)
#define MQ    (Qq*Bn)      // 1600

// ---------------------------------------------------------------------------
// Scratch: one big __device__ global (no cudaMalloc allowed)
// ---------------------------------------------------------------------------
constexpr size_t N_QWT   = 512*512;
constexpr size_t N_PRJWT = 512*512;
constexpr size_t N_WT11  = (size_t)K1*512;
constexpr size_t N_WT12  = (size_t)K1*512;
constexpr size_t N_WT21  = (size_t)K2*512;
constexpr size_t N_WT22  = (size_t)K2*512;
constexpr size_t N_KVWT  = 512*256;
constexpr size_t N_A1    = (size_t)M1*K1;
constexpr size_t N_A2    = (size_t)M2*K2;
constexpr size_t N_PQ    = (size_t)MQ*512;
constexpr size_t N_KEY1  = (size_t)M1*512;
constexpr size_t N_KEY2  = (size_t)M2*512;
constexpr size_t N_KV1   = (size_t)M1*256;
constexpr size_t N_KV2   = (size_t)M2*256;
constexpr size_t N_X     = (size_t)MQ*512;

constexpr size_t O_QWT   = 0;
constexpr size_t O_PRJWT = O_QWT   + N_QWT;
constexpr size_t O_WT11  = O_PRJWT + N_PRJWT;
constexpr size_t O_WT12  = O_WT11  + N_WT11;
constexpr size_t O_WT21  = O_WT12  + N_WT12;
constexpr size_t O_WT22  = O_WT21  + N_WT21;
constexpr size_t O_KWT1  = O_WT22  + N_WT22;
constexpr size_t O_VWT1  = O_KWT1  + N_KVWT;
constexpr size_t O_KWT2  = O_VWT1  + N_KVWT;
constexpr size_t O_VWT2  = O_KWT2  + N_KVWT;
constexpr size_t O_A1K   = O_VWT2  + N_KVWT;
constexpr size_t O_A1V   = O_A1K   + N_A1;
constexpr size_t O_A2K   = O_A1V   + N_A1;
constexpr size_t O_A2V   = O_A2K   + N_A2;
constexpr size_t O_PQ    = O_A2V   + N_A2;
constexpr size_t O_KEY1  = O_PQ    + N_PQ;
constexpr size_t O_VAL1  = O_KEY1  + N_KEY1;
constexpr size_t O_KEY2  = O_VAL1  + N_KEY1;
constexpr size_t O_VAL2  = O_KEY2  + N_KEY2;
constexpr size_t O_K1    = O_VAL2  + N_KEY2;
constexpr size_t O_V1    = O_K1    + N_KV1;
constexpr size_t O_K2    = O_V1    + N_KV1;
constexpr size_t O_V2    = O_K2    + N_KV2;
constexpr size_t O_VS1   = O_V2    + N_KV2;
constexpr size_t O_VS2   = O_VS1   + N_KV1;
constexpr size_t O_X     = O_VS2   + N_KV2;
constexpr size_t N_TOTAL = O_X     + N_X;

__device__ float g_scratch[N_TOTAL];

// ---------------------------------------------------------------------------
// packed f32x2 FMA (sm_103a: 3-reg FFMA is half-rate; f32x2 restores full rate)
// ---------------------------------------------------------------------------
__device__ __forceinline__ void fma2(float2& d, float2 a, float2 b) {
    unsigned long long& dd = reinterpret_cast<unsigned long long&>(d);
    unsigned long long aa = *reinterpret_cast<unsigned long long*>(&a);
    unsigned long long bb = *reinterpret_cast<unsigned long long*>(&b);
    asm("fma.rn.f32x2 %0, %1, %2, %0;" : "+l"(dd) : "l"(aa), "l"(bb));
}

// ---------------------------------------------------------------------------
// Weight transpose: wT[(p*Cin+ci)*Cout + c] = w[(c*Cin+ci)*P + p]
// (P=1 -> plain matrix transpose; P=KH*KW for conv weights reordered so the
//  GEMM K-dim is (patch_pos, ci) with ci fastest -> coalesced im2col loads)
// ---------------------------------------------------------------------------
__global__ void k_tw(const float* __restrict__ w, float* __restrict__ wT,
                     int P, int Cin, int Cout) {
    long long idx = (long long)blockIdx.x * 256 + threadIdx.x;
    long long total = (long long)P * Cin * Cout;
    if (idx >= total) return;
    int c = (int)(idx % Cout);
    long long kIdx = idx / Cout;
    int ci = (int)(kIdx % Cin);
    int p  = (int)(kIdx / Cin);
    wT[idx] = w[((long long)c * Cin + ci) * P + p];
}

// ---------------------------------------------------------------------------
// im2col for stride==kernel 'VALID' conv on a (B,N,C) token tensor viewed as
// (B,C,H,W).  A[m][(p*512)+ci], m=b*OH*OW+oy*OW+ox, p=ky*KS+kx
// ---------------------------------------------------------------------------
__global__ void k_im2col(const float* __restrict__ src, float* __restrict__ A,
                         int OH, int OW, int KS) {
    long long idx = (long long)blockIdx.x * 256 + threadIdx.x;
    long long total = (long long)Bn * OH * OW * KS * KS * Dm;
    if (idx >= total) return;
    int ci = (int)(idx & (Dm - 1));
    long long t = idx >> 9;
    int P = KS * KS;
    int p = (int)(t % P);
    long long m = t / P;
    int ox = (int)(m % OW);
    long long t2 = m / OW;
    int oy = (int)(t2 % OH);
    int b  = (int)(t2 / OH);
    int ky = p / KS, kx = p % KS;
    int y = oy * KS + ky, x = ox * KS + kx;
    A[idx] = src[((long long)(b * Nn + y * Ww + x)) * Dm + ci];
}

// ---------------------------------------------------------------------------
// SGEMM: C[M,N] = A[M,K] @ B[K,N] (+bias).  128x128 tile, BK=8, 8x8 microtile,
// f32x2 packed accumulation.  blockIdx.z selects one of up to 2 sub-problems.
// N must be a multiple of 128 (true for all call sites: 512 or 256).
// ---------------------------------------------------------------------------
struct GemmB {
    const float* A[2];
    const float* B[2];
    float*       C[2];
    const float* bias;
};

__global__ void __launch_bounds__(256) k_sgemm(int M, int N, int K, GemmB g) {
    __shared__ float sA[8][128];
    __shared__ float sB[8][128];
    const float* __restrict__ A = g.A[blockIdx.z];
    const float* __restrict__ B = g.B[blockIdx.z];
    float* __restrict__ C = g.C[blockIdx.z];
    int tid = threadIdx.x;
    int rowBase = blockIdx.y * 128;
    int colBase = blockIdx.x * 128;
    int aRow = tid >> 1;
    int aCol = (tid & 1) << 2;
    int bRow = tid >> 5;
    int bCol = (tid & 31) << 2;
    int tr = (tid >> 4) << 3;
    int tc = (tid & 15) << 3;

    float2 acc[8][4];
    #pragma unroll
    for (int i = 0; i < 8; i++)
        #pragma unroll
        for (int j = 0; j < 4; j++) acc[i][j] = make_float2(0.f, 0.f);

    bool aValid = (rowBase + aRow) < M;
    const float* aPtr = A + (size_t)(rowBase + aRow) * K + aCol;
    const float* bPtr = B + (size_t)bRow * N + colBase + bCol;

    for (int k0 = 0; k0 < K; k0 += 8) {
        float4 av = make_float4(0.f, 0.f, 0.f, 0.f);
        if (aValid) av = *(const float4*)(aPtr + k0);
        float4 bv = *(const float4*)(bPtr + (size_t)k0 * N);
        sA[aCol + 0][aRow] = av.x;
        sA[aCol + 1][aRow] = av.y;
        sA[aCol + 2][aRow] = av.z;
        sA[aCol + 3][aRow] = av.w;
        *(float4*)&sB[bRow][bCol] = bv;
        __syncthreads();
        #pragma unroll
        for (int kk = 0; kk < 8; kk++) {
            float4 a0 = *(const float4*)&sA[kk][tr];
            float4 a1 = *(const float4*)&sA[kk][tr + 4];
            float4 b0 = *(const float4*)&sB[kk][tc];
            float4 b1 = *(const float4*)&sB[kk][tc + 4];
            float ar[8] = {a0.x, a0.y, a0.z, a0.w, a1.x, a1.y, a1.z, a1.w};
            float2 br[4] = {make_float2(b0.x, b0.y), make_float2(b0.z, b0.w),
                            make_float2(b1.x, b1.y), make_float2(b1.z, b1.w)};
            #pragma unroll
            for (int i = 0; i < 8; i++) {
                float2 ap = make_float2(ar[i], ar[i]);
                #pragma unroll
                for (int j = 0; j < 4; j++) fma2(acc[i][j], ap, br[j]);
            }
        }
        __syncthreads();
    }

    const float* bias = g.bias;
    #pragma unroll
    for (int i = 0; i < 8; i++) {
        int r = rowBase + tr + i;
        if (r < M) {
            float* cp = C + (size_t)r * N + colBase + tc;
            #pragma unroll
            for (int j = 0; j < 4; j++) {
                float bx = 0.f, by = 0.f;
                if (bias) {
                    bx = bias[colBase + tc + 2 * j];
                    by = bias[colBase + tc + 2 * j + 1];
                }
                cp[2 * j]     = acc[i][j].x + bx;
                cp[2 * j + 1] = acc[i][j].y + by;
            }
        }
    }
}

// ---------------------------------------------------------------------------
// bias + LayerNorm(512) + relu6, in place on (rows, 512)
// ---------------------------------------------------------------------------
__device__ __forceinline__ float blockReduceSum256(float v, float* sbuf) {
    int lane = threadIdx.x & 31, w = threadIdx.x >> 5;
    #pragma unroll
    for (int off = 16; off; off >>= 1) v += __shfl_xor_sync(0xffffffffu, v, off);
    if (lane == 0) sbuf[w] = v;
    __syncthreads();
    float s = 0.f;
    #pragma unroll
    for (int t = 0; t < 8; t++) s += sbuf[t];
    __syncthreads();
    return s;
}

__global__ void __launch_bounds__(256) k_biasln(float* __restrict__ x,
                                                const float* __restrict__ cb,
                                                const float* __restrict__ g,
                                                const float* __restrict__ bb) {
    __shared__ float sbuf[8];
    int row = blockIdx.x, tid = threadIdx.x;
    float* xr = x + (size_t)row * 512;
    float v0 = xr[tid] + cb[tid];
    float v1 = xr[tid + 256] + cb[tid + 256];
    float s = blockReduceSum256(v0 + v1, sbuf);
    float mean = s * (1.f / 512.f);
    float d0 = v0 - mean, d1 = v1 - mean;
    float s2 = blockReduceSum256(d0 * d0 + d1 * d1, sbuf);
    float inv = rsqrtf(s2 * (1.f / 512.f) + 1e-5f);
    float y0 = d0 * inv * g[tid] + bb[tid];
    float y1 = d1 * inv * g[tid + 256] + bb[tid + 256];
    xr[tid]       = fminf(fmaxf(y0, 0.f), 6.f);
    xr[tid + 256] = fminf(fmaxf(y1, 0.f), 6.f);
}

// ---------------------------------------------------------------------------
// depthwise 3x3 (pad 1) on v viewed as (B, C2, hh, ww) + bias + residual add:
// vs[b,l,c] = v[b,l,c] + (dwconv(v)[b,c,y,x] + lb[c])
// ---------------------------------------------------------------------------
__global__ void k_dwadd(const float* __restrict__ v, float* __restrict__ vs,
                        const float* __restrict__ lw, const float* __restrict__ lb,
                        int hh, int ww) {
    int L = hh * ww;
    long long idx = (long long)blockIdx.x * 256 + threadIdx.x;
    long long total = (long long)Bn * L * C2;
    if (idx >= total) return;
    int c = (int)(idx & 255);
    int l = (int)((idx >> 8) % L);
    int b = (int)(idx / ((long long)L << 8));
    int y = l / ww, x = l % ww;
    float acc = lb[c];
    #pragma unroll
    for (int dy = 0; dy < 3; dy++) {
        int yy = y + dy - 1;
        if ((unsigned)yy >= (unsigned)hh) continue;
        #pragma unroll
        for (int dx = 0; dx < 3; dx++) {
            int xx = x + dx - 1;
            if ((unsigned)xx >= (unsigned)ww) continue;
            acc += v[(((long long)b * L + yy * ww + xx) << 8) + c] * lw[c * 9 + dy * 3 + dx];
        }
    }
    vs[idx] = v[idx] + acc;
}

// ---------------------------------------------------------------------------
// Attention: one block = (b, h, 8 queries).  Two-pass softmax with scores in
// shared (L<=1024).  Writes directly into the concatenated x buffer (Q,B,D)
// honoring the reference's raw-reshape index mapping.
// ---------------------------------------------------------------------------
__global__ void __launch_bounds__(256) k_attn(const float* __restrict__ Pq,
                                              const float* __restrict__ Kmat,
                                              const float* __restrict__ Vmat,
                                              float* __restrict__ xbuf,
                                              int L, int branch) {
    __shared__ float qv[8 * 64];
    __shared__ float sc[8 * 1024];
    __shared__ float red[8 * 8];
    int qt = blockIdx.x, h = blockIdx.y, b = blockIdx.z;
    int tid = threadIdx.x;
    int q0 = qt * 8;
    int hglob = h + branch * NH2;

    for (int i = tid; i < 512; i += 256) {
        int qi = i >> 6, d = i & 63;
        qv[i] = Pq[(((size_t)(b * Qq + q0 + qi) * NH + hglob) << 6) + d] * 0.125f;
    }
    __syncthreads();

    float mx[8];
    #pragma unroll
    for (int qi = 0; qi < 8; qi++) mx[qi] = -1e30f;

    for (int l = tid; l < L; l += 256) {
        const float4* kp = (const float4*)(Kmat + (((size_t)b * L + l) << 8) + (h << 6));
        float acc[8] = {0, 0, 0, 0, 0, 0, 0, 0};
        #pragma unroll
        for (int c4 = 0; c4 < 16; c4++) {
            float4 kk = kp[c4];
            #pragma unroll
            for (int qi = 0; qi < 8; qi++) {
                const float* qq = &qv[(qi << 6) + (c4 << 2)];
                acc[qi] += kk.x * qq[0] + kk.y * qq[1] + kk.z * qq[2] + kk.w * qq[3];
            }
        }
        #pragma unroll
        for (int qi = 0; qi < 8; qi++) {
            sc[(qi << 10) + l] = acc[qi];
            mx[qi] = fmaxf(mx[qi], acc[qi]);
        }
    }

    int lane = tid & 31, w = tid >> 5;
    // block-reduce max per query
    #pragma unroll
    for (int qi = 0; qi < 8; qi++) {
        float m = mx[qi];
        #pragma unroll
        for (int off = 16; off; off >>= 1) m = fmaxf(m, __shfl_xor_sync(0xffffffffu, m, off));
        mx[qi] = m;
    }
    if (lane == 0) {
        #pragma unroll
        for (int qi = 0; qi < 8; qi++) red[w * 8 + qi] = mx[qi];
    }
    __syncthreads();
    float bmax[8];
    #pragma unroll
    for (int qi = 0; qi < 8; qi++) {
        float m = red[qi];
        #pragma unroll
        for (int t = 1; t < 8; t++) m = fmaxf(m, red[t * 8 + qi]);
        bmax[qi] = m;
    }
    __syncthreads();

    float ls[8] = {0, 0, 0, 0, 0, 0, 0, 0};
    for (int l = tid; l < L; l += 256) {
        #pragma unroll
        for (int qi = 0; qi < 8; qi++) {
            float e = __expf(sc[(qi << 10) + l] - bmax[qi]);
            sc[(qi << 10) + l] = e;
            ls[qi] += e;
        }
    }
    #pragma unroll
    for (int qi = 0; qi < 8; qi++) {
        float v = ls[qi];
        #pragma unroll
        for (int off = 16; off; off >>= 1) v += __shfl_xor_sync(0xffffffffu, v, off);
        ls[qi] = v;
    }
    if (lane == 0) {
        #pragma unroll
        for (int qi = 0; qi < 8; qi++) red[w * 8 + qi] = ls[qi];
    }
    __syncthreads();
    float inv[8];
    #pragma unroll
    for (int qi = 0; qi < 8; qi++) {
        float s = 0.f;
        #pragma unroll
        for (int t = 0; t < 8; t++) s += red[t * 8 + qi];
        inv[qi] = 1.f / s;
    }
    __syncthreads();

    // phase 2: warp w handles d in [w*8, w*8+8)
    float acc2[8][8] = {};
    for (int l = lane; l < L; l += 32) {
        const float4* vp = (const float4*)(Vmat + (((size_t)b * L + l) << 8) + (h << 6) + (w << 3));
        float4 v0 = vp[0], v1 = vp[1];
        float pr[8];
        #pragma unroll
        for (int qi = 0; qi < 8; qi++) pr[qi] = sc[(qi << 10) + l];
        #pragma unroll
        for (int qi = 0; qi < 8; qi++) {
            acc2[qi][0] += pr[qi] * v0.x;
            acc2[qi][1] += pr[qi] * v0.y;
            acc2[qi][2] += pr[qi] * v0.z;
            acc2[qi][3] += pr[qi] * v0.w;
            acc2[qi][4] += pr[qi] * v1.x;
            acc2[qi][5] += pr[qi] * v1.y;
            acc2[qi][6] += pr[qi] * v1.z;
            acc2[qi][7] += pr[qi] * v1.w;
        }
    }
    #pragma unroll
    for (int qi = 0; qi < 8; qi++)
        #pragma unroll
        for (int j = 0; j < 8; j++) {
            float v = acc2[qi][j];
            #pragma unroll
            for (int off = 16; off; off >>= 1) v += __shfl_xor_sync(0xffffffffu, v, off);
            acc2[qi][j] = v;
        }
    if (lane == 0) {
        #pragma unroll
        for (int qi = 0; qi < 8; qi++)
            #pragma unroll
            for (int j = 0; j < 8; j++) {
                int d = (w << 3) + j;
                // raw-reshape mapping: (B,Q,NH2,HD) flat -> (Q,B,C2)
                int f = (((b * Qq + q0 + qi) << 2) + h) * 64 + d;
                int q2 = f >> 11;
                int rem = f & 2047;
                int b2 = rem >> 8;
                int c2 = rem & 255;
                xbuf[((size_t)(q2 * Bn + b2)) * Dm + branch * C2 + c2] = acc2[qi][j] * inv[qi];
            }
    }
}

// ---------------------------------------------------------------------------
// host side
// ---------------------------------------------------------------------------
static void launch_gemm(int M, int N, int K,
                        const float* A0, const float* B0, float* C0,
                        const float* A1 = nullptr, const float* B1 = nullptr,
                        float* C1 = nullptr, const float* bias = nullptr) {
    GemmB g;
    g.A[0] = A0; g.A[1] = A1;
    g.B[0] = B0; g.B[1] = B1;
    g.C[0] = C0; g.C[1] = C1;
    g.bias = bias;
    int z = A1 ? 2 : 1;
    dim3 grid(N / 128, (M + 127) / 128, z);
    k_sgemm<<<grid, 256>>>(M, N, K, g);
}

extern "C" void kernel_launch(void* const* d_in, const int* in_sizes, int n_in,
                              void* d_out, int out_size) {
    const float* query = (const float*)d_in[0];
    const float* key   = (const float*)d_in[1];
    const float* value = (const float*)d_in[2];
    const float* q_w   = (const float*)d_in[3];
    const float* sr11w = (const float*)d_in[4];
    const float* sr11b = (const float*)d_in[5];
    const float* n11g  = (const float*)d_in[6];
    const float* n11b  = (const float*)d_in[7];
    const float* sr12w = (const float*)d_in[8];
    const float* sr12b = (const float*)d_in[9];
    const float* n12g  = (const float*)d_in[10];
    const float* n12b  = (const float*)d_in[11];
    const float* sr21w = (const float*)d_in[12];
    const float* sr21b = (const float*)d_in[13];
    const float* n21g  = (const float*)d_in[14];
    const float* n21b  = (const float*)d_in[15];
    const float* sr22w = (const float*)d_in[16];
    const float* sr22b = (const float*)d_in[17];
    const float* n22g  = (const float*)d_in[18];
    const float* n22b  = (const float*)d_in[19];
    const float* k1w   = (const float*)d_in[20];
    const float* v1w   = (const float*)d_in[21];
    const float* k2w   = (const float*)d_in[22];
    const float* v2w   = (const float*)d_in[23];
    const float* lc1w  = (const float*)d_in[24];
    const float* lc1b  = (const float*)d_in[25];
    const float* lc2w  = (const float*)d_in[26];
    const float* lc2b  = (const float*)d_in[27];
    const float* projw = (const float*)d_in[28];
    const float* projb = (const float*)d_in[29];
    float* out = (float*)d_out;

    float* base;
    cudaGetSymbolAddress((void**)&base, g_scratch);
    float* qwT   = base + O_QWT;
    float* prjwT = base + O_PRJWT;
    float* wt11  = base + O_WT11;
    float* wt12  = base + O_WT12;
    float* wt21  = base + O_WT21;
    float* wt22  = base + O_WT22;
    float* kwT1  = base + O_KWT1;
    float* vwT1  = base + O_VWT1;
    float* kwT2  = base + O_KWT2;
    float* vwT2  = base + O_VWT2;
    float* a1k   = base + O_A1K;
    float* a1v   = base + O_A1V;
    float* a2k   = base + O_A2K;
    float* a2v   = base + O_A2V;
    float* pq    = base + O_PQ;
    float* key1  = base + O_KEY1;
    float* val1  = base + O_VAL1;
    float* key2  = base + O_KEY2;
    float* val2  = base + O_VAL2;
    float* k1b   = base + O_K1;
    float* v1b   = base + O_V1;
    float* k2b   = base + O_K2;
    float* v2b   = base + O_V2;
    float* vs1   = base + O_VS1;
    float* vs2   = base + O_VS2;
    float* xbuf  = base + O_X;

    // --- weight transposes ---
    auto twgrid = [](long long total) { return (unsigned)((total + 255) / 256); };
    k_tw<<<twgrid((long long)512 * 512), 256>>>(q_w,   qwT,   1,  512, 512);
    k_tw<<<twgrid((long long)512 * 512), 256>>>(projw, prjwT, 1,  512, 512);
    k_tw<<<twgrid((long long)K1 * 512), 256>>>(sr11w, wt11, 16, 512, 512);
    k_tw<<<twgrid((long long)K1 * 512), 256>>>(sr12w, wt12, 16, 512, 512);
    k_tw<<<twgrid((long long)K2 * 512), 256>>>(sr21w, wt21, 4,  512, 512);
    k_tw<<<twgrid((long long)K2 * 512), 256>>>(sr22w, wt22, 4,  512, 512);
    k_tw<<<twgrid((long long)512 * 256), 256>>>(k1w, kwT1, 1, 512, 256);
    k_tw<<<twgrid((long long)512 * 256), 256>>>(v1w, vwT1, 1, 512, 256);
    k_tw<<<twgrid((long long)512 * 256), 256>>>(k2w, kwT2, 1, 512, 256);
    k_tw<<<twgrid((long long)512 * 256), 256>>>(v2w, vwT2, 1, 512, 256);

    // --- im2col ---
    k_im2col<<<twgrid((long long)M1 * K1), 256>>>(key,   a1k, 16, 16, 4);
    k_im2col<<<twgrid((long long)M1 * K1), 256>>>(value, a1v, 16, 16, 4);
    k_im2col<<<twgrid((long long)M2 * K2), 256>>>(key,   a2k, 32, 32, 2);
    k_im2col<<<twgrid((long long)M2 * K2), 256>>>(value, a2v, 32, 32, 2);

    // --- q projection ---
    launch_gemm(MQ, 512, 512, query, qwT, pq);

    // --- reduction convs as GEMMs (paired in z) ---
    launch_gemm(M1, 512, K1, a1k, wt11, key1, a1v, wt12, val1);
    launch_gemm(M2, 512, K2, a2k, wt21, key2, a2v, wt22, val2);

    // --- bias + LN + relu6 ---
    k_biasln<<<M1, 256>>>(key1, sr11b, n11g, n11b);
    k_biasln<<<M1, 256>>>(val1, sr12b, n12g, n12b);
    k_biasln<<<M2, 256>>>(key2, sr21b, n21g, n21b);
    k_biasln<<<M2, 256>>>(val2, sr22b, n22g, n22b);

    // --- K/V head projections ---
    launch_gemm(M1, 256, 512, key1, kwT1, k1b, val1, vwT1, v1b);
    launch_gemm(M2, 256, 512, key2, kwT2, k2b, val2, vwT2, v2b);

    // --- depthwise local V + residual ---
    k_dwadd<<<twgrid((long long)M1 * 256), 256>>>(v1b, vs1, lc1w, lc1b, 16, 16);
    k_dwadd<<<twgrid((long long)M2 * 256), 256>>>(v2b, vs2, lc2w, lc2b, 32, 32);

    // --- attention branches (write into concat buffer) ---
    k_attn<<<dim3(Qq / 8, NH2, Bn), 256>>>(pq, k1b, vs1, xbuf, L1, 0);
    k_attn<<<dim3(Qq / 8, NH2, Bn), 256>>>(pq, k2b, vs2, xbuf, L2, 1);

    // --- final projection (+bias) straight to output ---
    launch_gemm(MQ, 512, 512, xbuf, prjwT, out, nullptr, nullptr, nullptr, projb);

    (void)in_sizes; (void)n_in; (void)out_size;
}

// round 3
// speedup vs baseline: 1.3124x; 1.3124x over previous
#include <cuda_runtime.h>
#include <cuda_bf16.h>
#include <cstdint>
#include <cstddef>

#if defined(__CUDA_ARCH_FEAT_SM103_ALL)
#define USE_TC 1
#else
#define USE_TC 0
#endif

// ---------------------------------------------------------------------------
// Problem constants
// ---------------------------------------------------------------------------
#define Dm    512
#define Bn    8
#define Hh    64
#define Ww    64
#define Nn    (Hh*Ww)      // 4096
#define Qq    200
#define C2    256
#define NH    8
#define NH2   4
#define HD    64
#define L1    256          // 16x16
#define L2    1024         // 32x32
#define M1    (Bn*L1)      // 2048
#define M2    (Bn*L2)      // 8192
#define K1    (Dm*16)      // 8192 (4x4 patch)
#define K2    (Dm*4)       // 2048 (2x2 patch)
#define MQ    (Qq*Bn)      // 1600

// ---------------------------------------------------------------------------
// Scratch (static __device__; no cudaMalloc allowed)
// ---------------------------------------------------------------------------
constexpr size_t SZ_QW   = 512u*512u;
constexpr size_t SZ_W1   = 512u*8192u;
constexpr size_t SZ_W2   = 512u*2048u;
constexpr size_t SZ_KVW  = 256u*512u;
constexpr size_t SZ_A    = 2048u*8192u;
constexpr size_t SZ_QC   = (size_t)MQ*512u;
constexpr size_t SZ_K1C  = (size_t)M1*512u;
constexpr size_t SZ_K2C  = (size_t)M2*512u;

constexpr size_t B_QWH = 0;
constexpr size_t B_QWL = B_QWH + SZ_QW;
constexpr size_t B_PWH = B_QWL + SZ_QW;
constexpr size_t B_PWL = B_PWH + SZ_QW;
constexpr size_t B_W11H = B_PWL + SZ_QW;
constexpr size_t B_W11L = B_W11H + SZ_W1;
constexpr size_t B_W12H = B_W11L + SZ_W1;
constexpr size_t B_W12L = B_W12H + SZ_W1;
constexpr size_t B_W21H = B_W12L + SZ_W1;
constexpr size_t B_W21L = B_W21H + SZ_W2;
constexpr size_t B_W22H = B_W21L + SZ_W2;
constexpr size_t B_W22L = B_W22H + SZ_W2;
constexpr size_t B_KW1H = B_W22L + SZ_W2;
constexpr size_t B_KW1L = B_KW1H + SZ_KVW;
constexpr size_t B_VW1H = B_KW1L + SZ_KVW;
constexpr size_t B_VW1L = B_VW1H + SZ_KVW;
constexpr size_t B_KW2H = B_VW1L + SZ_KVW;
constexpr size_t B_KW2L = B_KW2H + SZ_KVW;
constexpr size_t B_VW2H = B_KW2L + SZ_KVW;
constexpr size_t B_VW2L = B_VW2H + SZ_KVW;
constexpr size_t B_A1KH = B_VW2L + SZ_KVW;
constexpr size_t B_A1KL = B_A1KH + SZ_A;
constexpr size_t B_A1VH = B_A1KL + SZ_A;
constexpr size_t B_A1VL = B_A1VH + SZ_A;
constexpr size_t B_A2KH = B_A1VL + SZ_A;
constexpr size_t B_A2KL = B_A2KH + SZ_A;
constexpr size_t B_A2VH = B_A2KL + SZ_A;
constexpr size_t B_A2VL = B_A2VH + SZ_A;
constexpr size_t B_QCH  = B_A2VL + SZ_A;
constexpr size_t B_QCL  = B_QCH + SZ_QC;
constexpr size_t B_K1CH = B_QCL + SZ_QC;
constexpr size_t B_K1CL = B_K1CH + SZ_K1C;
constexpr size_t B_V1CH = B_K1CL + SZ_K1C;
constexpr size_t B_V1CL = B_V1CH + SZ_K1C;
constexpr size_t B_K2CH = B_V1CL + SZ_K1C;
constexpr size_t B_K2CL = B_K2CH + SZ_K2C;
constexpr size_t B_V2CH = B_K2CL + SZ_K2C;
constexpr size_t B_V2CL = B_V2CH + SZ_K2C;
constexpr size_t B_XCH  = B_V2CL + SZ_K2C;
constexpr size_t B_XCL  = B_XCH + SZ_QC;
constexpr size_t B_TOTAL = B_XCL + SZ_QC;

__device__ __align__(16) __nv_bfloat16 g_bf[B_TOTAL];

constexpr size_t F_PQ  = 0;
constexpr size_t F_C1K = F_PQ  + (size_t)MQ*512;
constexpr size_t F_C1V = F_C1K + (size_t)M1*512;
constexpr size_t F_C2K = F_C1V + (size_t)M1*512;
constexpr size_t F_C2V = F_C2K + (size_t)M2*512;
constexpr size_t F_KB1 = F_C2V + (size_t)M2*512;
constexpr size_t F_VB1 = F_KB1 + (size_t)M1*256;
constexpr size_t F_KB2 = F_VB1 + (size_t)M1*256;
constexpr size_t F_VB2 = F_KB2 + (size_t)M2*256;
constexpr size_t F_VS1 = F_VB2 + (size_t)M2*256;
constexpr size_t F_VS2 = F_VS1 + (size_t)M1*256;
constexpr size_t F_X   = F_VS2 + (size_t)M2*256;
constexpr size_t F_TOTAL = F_X + (size_t)MQ*512;

__device__ __align__(16) float g_f[F_TOTAL];

// ---------------------------------------------------------------------------
// helpers
// ---------------------------------------------------------------------------
__device__ __forceinline__ uint32_t smem_u32(const void* p) {
    uint32_t a;
    asm("{ .reg .u64 t; cvta.to.shared.u64 t, %1; cvt.u32.u64 %0, t; }" : "=r"(a) : "l"(p));
    return a;
}

__device__ __forceinline__ void cvt_hl(float x, __nv_bfloat16& h, __nv_bfloat16& l) {
    h = __float2bfloat16(x);
    l = __float2bfloat16(x - __bfloat162float(h));
}

#define MMA_BF16(c, a, b) \
    asm volatile("mma.sync.aligned.m16n8k16.row.col.f32.bf16.bf16.f32 " \
        "{%0,%1,%2,%3}, {%4,%5,%6,%7}, {%8,%9}, {%0,%1,%2,%3};" \
        : "+f"((c)[0]), "+f"((c)[1]), "+f"((c)[2]), "+f"((c)[3]) \
        : "r"((a)[0]), "r"((a)[1]), "r"((a)[2]), "r"((a)[3]), \
          "r"((b)[0]), "r"((b)[1]))

#if USE_TC
__device__ __forceinline__ uint32_t elect1() {
    uint32_t p;
    asm volatile("{\n\t.reg .pred p;\n\telect.sync _|p, 0xFFFFFFFF;\n\tselp.b32 %0, 1, 0, p;\n\t}" : "=r"(p));
    return p;
}
#define MBAR_INIT(a, c) asm volatile("mbarrier.init.shared.b64 [%0], %1;" :: "r"(a), "r"(c) : "memory")
#define MBAR_INVAL(a)   asm volatile("mbarrier.inval.shared.b64 [%0];" :: "r"(a) : "memory")
__device__ __forceinline__ void mbar_wait(uint32_t addr, uint32_t parity) {
    uint32_t done;
    asm volatile("{\n\t.reg .pred p;\n\t"
        "mbarrier.try_wait.parity.acquire.cta.shared::cta.b64 p, [%1], %2;\n\t"
        "selp.b32 %0, 1, 0, p;\n\t}" : "=r"(done) : "r"(addr), "r"(parity) : "memory");
    while (!done) {
        asm volatile("{\n\t.reg .pred p;\n\t"
            "mbarrier.try_wait.parity.acquire.cta.shared::cta.b64 p, [%1], %2, 0x989680;\n\t"
            "selp.b32 %0, 1, 0, p;\n\t}" : "=r"(done) : "r"(addr), "r"(parity) : "memory");
    }
}
#define TC_ALLOC(sa, n)   asm volatile("tcgen05.alloc.cta_group::1.sync.aligned.shared::cta.b32 [%0], %1;" :: "r"(sa), "r"(n) : "memory")
#define TC_DEALLOC(t, n)  asm volatile("tcgen05.dealloc.cta_group::1.sync.aligned.b32 %0, %1;" :: "r"(t), "r"(n))
#define TC_RELINQ()       asm volatile("tcgen05.relinquish_alloc_permit.cta_group::1.sync.aligned;")
#define TC_COMMIT(mb)     asm volatile("tcgen05.commit.cta_group::1.mbarrier::arrive::one.shared::cluster.b64 [%0];" :: "r"(mb) : "memory")
#define TC_WAIT_LD()      asm volatile("tcgen05.wait::ld.sync.aligned;" ::: "memory")
#define TC_FENCE_AFTER()  asm volatile("tcgen05.fence::after_thread_sync;" ::: "memory")
#define FENCE_ASYNC_SH()  asm volatile("fence.proxy.async.shared::cta;" ::: "memory")
#define TC_LD_X32(r, ta) \
    asm volatile( \
        "tcgen05.ld.sync.aligned.32x32b.x32.b32 " \
        "{%0, %1, %2, %3, %4, %5, %6, %7, " \
        " %8, %9, %10, %11, %12, %13, %14, %15, " \
        " %16, %17, %18, %19, %20, %21, %22, %23, " \
        " %24, %25, %26, %27, %28, %29, %30, %31}, [%32];" \
        : "=r"((r)[0]),  "=r"((r)[1]),  "=r"((r)[2]),  "=r"((r)[3]), \
          "=r"((r)[4]),  "=r"((r)[5]),  "=r"((r)[6]),  "=r"((r)[7]), \
          "=r"((r)[8]),  "=r"((r)[9]),  "=r"((r)[10]), "=r"((r)[11]), \
          "=r"((r)[12]), "=r"((r)[13]), "=r"((r)[14]), "=r"((r)[15]), \
          "=r"((r)[16]), "=r"((r)[17]), "=r"((r)[18]), "=r"((r)[19]), \
          "=r"((r)[20]), "=r"((r)[21]), "=r"((r)[22]), "=r"((r)[23]), \
          "=r"((r)[24]), "=r"((r)[25]), "=r"((r)[26]), "=r"((r)[27]), \
          "=r"((r)[28]), "=r"((r)[29]), "=r"((r)[30]), "=r"((r)[31]) \
        : "r"(ta))
static constexpr uint64_t DESC_SW128 =
    (uint64_t(2) << 61) | (uint64_t(1) << 46) | (uint64_t(64) << 32) | (uint64_t(1) << 16);
#define MK_DESC(sa) (DESC_SW128 | ((uint64_t)((sa) >> 4) & 0x3FFF))
#define IDESC_BF16_128 0x08200490u
__device__ __forceinline__ void mma_f16_ss(uint32_t d, uint64_t ad, uint64_t bd, uint32_t en) {
    asm volatile(
        "{\n\t.reg .pred p;\n\tsetp.ne.u32 p, %5, 0;\n\t"
        "tcgen05.mma.cta_group::1.kind::f16 [%0], %1, %2, %3, {%4, %4, %4, %4}, p;\n\t}"
        :: "r"(d), "l"(ad), "l"(bd), "r"(IDESC_BF16_128), "r"(0u), "r"(en) : "memory");
}
#endif // USE_TC

// ---------------------------------------------------------------------------
// Elementwise converters
// ---------------------------------------------------------------------------
__global__ void k_cvt(const float* __restrict__ x, __nv_bfloat16* __restrict__ h,
                      __nv_bfloat16* __restrict__ l, long long n) {
    long long i = (long long)blockIdx.x * 256 + threadIdx.x;
    if (i >= n) return;
    cvt_hl(x[i], h[i], l[i]);
}

// conv weight [Cout][Cin][P] -> Bt[co][p*Cin+ci] hi/lo
__global__ void k_twcv(const float* __restrict__ w, __nv_bfloat16* __restrict__ bh,
                       __nv_bfloat16* __restrict__ bl, int P, int Cin, int Cout) {
    long long idx = (long long)blockIdx.x * 256 + threadIdx.x;
    long long total = (long long)Cout * P * Cin;
    if (idx >= total) return;
    int ci = (int)(idx % Cin);
    long long t = idx / Cin;
    int p = (int)(t % P);
    int co = (int)(t / P);
    float v = w[((long long)co * Cin + ci) * P + p];
    cvt_hl(v, bh[idx], bl[idx]);
}

// im2col + hi/lo convert
__global__ void k_im2col_bf(const float* __restrict__ src,
                            __nv_bfloat16* __restrict__ Ah,
                            __nv_bfloat16* __restrict__ Al,
                            int OH, int OW, int KS) {
    long long idx = (long long)blockIdx.x * 256 + threadIdx.x;
    long long total = (long long)Bn * OH * OW * KS * KS * Dm;
    if (idx >= total) return;
    int ci = (int)(idx & (Dm - 1));
    long long t = idx >> 9;
    int P = KS * KS;
    int p = (int)(t % P);
    long long m = t / P;
    int ox = (int)(m % OW);
    long long t2 = m / OW;
    int oy = (int)(t2 % OH);
    int b  = (int)(t2 / OH);
    int ky = p / KS, kx = p % KS;
    int y = oy * KS + ky, x = ox * KS + kx;
    float v = src[((long long)(b * Nn + y * Ww + x)) * Dm + ci];
    cvt_hl(v, Ah[idx], Al[idx]);
}

// ---------------------------------------------------------------------------
// GEMM: C[M,N] = A[M,K] @ Bt[N,K]^T (+bias), bf16 hi/lo x3 compensation,
// fp32 accum. tcgen05 when the arch-specific target is available, else
// mma.sync (HMMA) + cp.async pipeline. 128x128 tile, 256 threads.
// ---------------------------------------------------------------------------
struct GemmT {
    const __nv_bfloat16 *Ah[2], *Al[2], *Bh[2], *Bl[2];
    float* C[2];
    const float* bias;
};

#define SMEM_BYTES 132096

__global__ void __launch_bounds__(256) k_gemm(int M, int N, int K, GemmT g) {
    extern __shared__ char gsm[];
    int z = blockIdx.z;
    const __nv_bfloat16* Ah = g.Ah[z];
    const __nv_bfloat16* Al = g.Al[z];
    const __nv_bfloat16* Bh = g.Bh[z];
    const __nv_bfloat16* Bl = g.Bl[z];
    int rowBase = blockIdx.y * 128;
    int colBase = blockIdx.x * 128;
    int tid = threadIdx.x, wid = tid >> 5, lane = tid & 31;
    uint32_t sb = smem_u32(gsm);

#if USE_TC
    // ---- tcgen05 path ----
    #define SM_MBAR 0
    #define SM_TPTR 16
    #define SM_BUF  1024
    #define TILE_B  16384
    #define BUF_B   65536
    if (tid == 0) {
        MBAR_INIT(sb + SM_MBAR, 1);
        MBAR_INIT(sb + SM_MBAR + 8, 1);
    }
    if (wid == 0) {
        TC_ALLOC(sb + SM_TPTR, 128);
        TC_RELINQ();
    }
    __syncthreads();
    uint32_t tmem;
    asm volatile("ld.shared.b32 %0, [%1];" : "=r"(tmem) : "r"(sb + SM_TPTR));

    int nch = K >> 6;
    int ph[2] = {0, 0};
    for (int c = 0; c < nch; c++) {
        int p = c & 1;
        if (c >= 2) {
            mbar_wait(sb + SM_MBAR + p * 8, ph[p]);
            ph[p] ^= 1;
        }
        char* bufc = gsm + SM_BUF + p * BUF_B;
        int kb = c << 6;
        #pragma unroll 4
        for (int i = tid; i < 1024; i += 256) {
            int r = i >> 3;
            int k4 = (i & 7) << 4;
            uint32_t off = (uint32_t)(r << 7) + k4;
            uint32_t sw = off ^ ((off >> 3) & 0x70);
            int grow = rowBase + r;
            uint4 vh = make_uint4(0, 0, 0, 0), vl = make_uint4(0, 0, 0, 0);
            if (grow < M) {
                size_t bo = ((size_t)grow * K + kb) * 2 + k4;
                vh = *(const uint4*)((const char*)Ah + bo);
                vl = *(const uint4*)((const char*)Al + bo);
            }
            *(uint4*)(bufc + sw) = vh;
            *(uint4*)(bufc + TILE_B + sw) = vl;
            size_t bo2 = ((size_t)(colBase + r) * K + kb) * 2 + k4;
            *(uint4*)(bufc + 2 * TILE_B + sw) = *(const uint4*)((const char*)Bh + bo2);
            *(uint4*)(bufc + 3 * TILE_B + sw) = *(const uint4*)((const char*)Bl + bo2);
        }
        FENCE_ASYNC_SH();
        __syncthreads();
        if (wid == 0 && elect1()) {
            uint32_t bufs = sb + SM_BUF + p * BUF_B;
            uint64_t adh = MK_DESC(bufs);
            uint64_t adl = MK_DESC(bufs + TILE_B);
            uint64_t bdh = MK_DESC(bufs + 2 * TILE_B);
            uint64_t bdl = MK_DESC(bufs + 3 * TILE_B);
            #pragma unroll
            for (int ks = 0; ks < 4; ks++) {
                uint32_t en0 = (c == 0 && ks == 0) ? 0u : 1u;
                mma_f16_ss(tmem, adh + ks * 2, bdh + ks * 2, en0);
                mma_f16_ss(tmem, adh + ks * 2, bdl + ks * 2, 1u);
                mma_f16_ss(tmem, adl + ks * 2, bdh + ks * 2, 1u);
            }
            TC_COMMIT(sb + SM_MBAR + p * 8);
        }
        __syncthreads();
    }
    int pl = (nch - 1) & 1;
    mbar_wait(sb + SM_MBAR + pl * 8, ph[pl]);
    TC_FENCE_AFTER();

    int sub = wid & 3, half = wid >> 2;
    int growE = rowBase + sub * 32 + lane;
    const float* bias = g.bias;
    float* C = g.C[z];
    #pragma unroll
    for (int cb = 0; cb < 2; cb++) {
        uint32_t regs[32];
        int c0 = half * 64 + cb * 32;
        TC_LD_X32(regs, tmem + c0);
        TC_WAIT_LD();
        if (growE < M) {
            float* cp = C + (size_t)growE * N + colBase + c0;
            if (bias) {
                const float* bp = bias + colBase + c0;
                #pragma unroll
                for (int j = 0; j < 32; j++) cp[j] = __uint_as_float(regs[j]) + bp[j];
            } else {
                #pragma unroll
                for (int j = 0; j < 32; j++) cp[j] = __uint_as_float(regs[j]);
            }
        }
    }
    __syncthreads();
    if (tid == 0) {
        MBAR_INVAL(sb + SM_MBAR);
        MBAR_INVAL(sb + SM_MBAR + 8);
    }
    __syncthreads();
    if (wid == 0) TC_DEALLOC(tmem, 128);

#else
    // ---- mma.sync (HMMA) path: BK=32, cp.async double buffer ----
    // SMEM stage layout: 4 planes (Ah, Al, Bh, Bl), each 128 rows x 40 bf16 (80B)
    const int PSB = 128 * 80;      // plane stride bytes (10240)
    const int SSB = 4 * PSB;       // stage stride (40960)
    int wm = wid & 1, wn = wid >> 1;

    const __nv_bfloat16* srcs[4] = {Ah, Al, Bh, Bl};

    auto issue = [&](int stage, int kb) {
        #pragma unroll
        for (int t = 0; t < 8; t++) {
            int cid = tid + t * 256;
            int plane = cid >> 9;          // 512 chunks per plane
            int r = (cid >> 2) & 127;
            int ch = cid & 3;
            bool isB = plane >= 2;
            int grow = (isB ? colBase : rowBase) + r;
            int valid = (isB || grow < M) ? 16 : 0;
            int growc = valid ? grow : 0;
            const char* gp = (const char*)srcs[plane] + ((size_t)growc * K + kb + ch * 8) * 2;
            uint32_t sa = sb + stage * SSB + plane * PSB + r * 80 + ch * 16;
            asm volatile("cp.async.cg.shared.global [%0], [%1], 16, %2;"
                         :: "r"(sa), "l"(gp), "r"(valid) : "memory");
        }
        asm volatile("cp.async.commit_group;" ::: "memory");
    };

    float acc[4][4][4];
    #pragma unroll
    for (int a = 0; a < 4; a++)
        #pragma unroll
        for (int b = 0; b < 4; b++)
            #pragma unroll
            for (int c = 0; c < 4; c++) acc[a][b][c] = 0.f;

    int niter = K >> 5;
    issue(0, 0);
    int r0 = lane >> 2, koff = (lane & 3) * 2;

    for (int it = 0; it < niter; it++) {
        if (it + 1 < niter) {
            issue((it + 1) & 1, (it + 1) << 5);
            asm volatile("cp.async.wait_group 1;" ::: "memory");
        } else {
            asm volatile("cp.async.wait_group 0;" ::: "memory");
        }
        __syncthreads();
        const char* sbase = gsm + (it & 1) * SSB;
        const char* pAh = sbase;
        const char* pAl = sbase + PSB;
        const char* pBh = sbase + 2 * PSB;
        const char* pBl = sbase + 3 * PSB;

        #pragma unroll
        for (int kk = 0; kk < 32; kk += 16) {
            uint32_t aH[4][4], aL[4][4], bH[4][2], bL[4][2];
            int c0b = (kk + koff) * 2, c8b = (kk + koff + 8) * 2;
            #pragma unroll
            for (int mt = 0; mt < 4; mt++) {
                int row = wm * 64 + mt * 16 + r0;
                aH[mt][0] = *(const uint32_t*)(pAh + row * 80 + c0b);
                aH[mt][1] = *(const uint32_t*)(pAh + (row + 8) * 80 + c0b);
                aH[mt][2] = *(const uint32_t*)(pAh + row * 80 + c8b);
                aH[mt][3] = *(const uint32_t*)(pAh + (row + 8) * 80 + c8b);
                aL[mt][0] = *(const uint32_t*)(pAl + row * 80 + c0b);
                aL[mt][1] = *(const uint32_t*)(pAl + (row + 8) * 80 + c0b);
                aL[mt][2] = *(const uint32_t*)(pAl + row * 80 + c8b);
                aL[mt][3] = *(const uint32_t*)(pAl + (row + 8) * 80 + c8b);
            }
            #pragma unroll
            for (int nt = 0; nt < 4; nt++) {
                int row = wn * 32 + nt * 8 + r0;
                bH[nt][0] = *(const uint32_t*)(pBh + row * 80 + c0b);
                bH[nt][1] = *(const uint32_t*)(pBh + row * 80 + c8b);
                bL[nt][0] = *(const uint32_t*)(pBl + row * 80 + c0b);
                bL[nt][1] = *(const uint32_t*)(pBl + row * 80 + c8b);
            }
            #pragma unroll
            for (int mt = 0; mt < 4; mt++)
                #pragma unroll
                for (int nt = 0; nt < 4; nt++) {
                    MMA_BF16(acc[mt][nt], aH[mt], bH[nt]);
                    MMA_BF16(acc[mt][nt], aH[mt], bL[nt]);
                    MMA_BF16(acc[mt][nt], aL[mt], bH[nt]);
                }
        }
        __syncthreads();
    }

    const float* bias = g.bias;
    float* C = g.C[z];
    #pragma unroll
    for (int mt = 0; mt < 4; mt++) {
        #pragma unroll
        for (int nt = 0; nt < 4; nt++) {
            int m0 = rowBase + wm * 64 + mt * 16 + r0;
            int n0 = colBase + wn * 32 + nt * 8 + (lane & 3) * 2;
            float bx = 0.f, by = 0.f;
            if (bias) { bx = bias[n0]; by = bias[n0 + 1]; }
            if (m0 < M) {
                float2 v = make_float2(acc[mt][nt][0] + bx, acc[mt][nt][1] + by);
                *(float2*)(C + (size_t)m0 * N + n0) = v;
            }
            if (m0 + 8 < M) {
                float2 v = make_float2(acc[mt][nt][2] + bx, acc[mt][nt][3] + by);
                *(float2*)(C + (size_t)(m0 + 8) * N + n0) = v;
            }
        }
    }
#endif
}

// ---------------------------------------------------------------------------
// bias + LayerNorm(512) + relu6 -> bf16 hi/lo planes
// ---------------------------------------------------------------------------
__device__ __forceinline__ float blockReduceSum256(float v, float* sbuf) {
    int lane = threadIdx.x & 31, w = threadIdx.x >> 5;
    #pragma unroll
    for (int off = 16; off; off >>= 1) v += __shfl_xor_sync(0xffffffffu, v, off);
    if (lane == 0) sbuf[w] = v;
    __syncthreads();
    float s = 0.f;
    #pragma unroll
    for (int t = 0; t < 8; t++) s += sbuf[t];
    __syncthreads();
    return s;
}

__global__ void __launch_bounds__(256) k_biasln(const float* __restrict__ x,
                                                const float* __restrict__ cb,
                                                const float* __restrict__ g,
                                                const float* __restrict__ bb,
                                                __nv_bfloat16* __restrict__ oh,
                                                __nv_bfloat16* __restrict__ ol) {
    __shared__ float sbuf[8];
    int row = blockIdx.x, tid = threadIdx.x;
    const float* xr = x + (size_t)row * 512;
    float v0 = xr[tid] + cb[tid];
    float v1 = xr[tid + 256] + cb[tid + 256];
    float s = blockReduceSum256(v0 + v1, sbuf);
    float mean = s * (1.f / 512.f);
    float d0 = v0 - mean, d1 = v1 - mean;
    float s2 = blockReduceSum256(d0 * d0 + d1 * d1, sbuf);
    float inv = rsqrtf(s2 * (1.f / 512.f) + 1e-5f);
    float y0 = d0 * inv * g[tid] + bb[tid];
    float y1 = d1 * inv * g[tid + 256] + bb[tid + 256];
    y0 = fminf(fmaxf(y0, 0.f), 6.f);
    y1 = fminf(fmaxf(y1, 0.f), 6.f);
    cvt_hl(y0, oh[(size_t)row * 512 + tid],       ol[(size_t)row * 512 + tid]);
    cvt_hl(y1, oh[(size_t)row * 512 + tid + 256], ol[(size_t)row * 512 + tid + 256]);
}

// ---------------------------------------------------------------------------
// depthwise 3x3 (pad 1) + bias + residual add
// ---------------------------------------------------------------------------
__global__ void k_dwadd(const float* __restrict__ v, float* __restrict__ vs,
                        const float* __restrict__ lw, const float* __restrict__ lb,
                        int hh, int ww) {
    int L = hh * ww;
    long long idx = (long long)blockIdx.x * 256 + threadIdx.x;
    long long total = (long long)Bn * L * C2;
    if (idx >= total) return;
    int c = (int)(idx & 255);
    int l = (int)((idx >> 8) % L);
    int b = (int)(idx / ((long long)L << 8));
    int y = l / ww, x = l % ww;
    float acc = lb[c];
    #pragma unroll
    for (int dy = 0; dy < 3; dy++) {
        int yy = y + dy - 1;
        if ((unsigned)yy >= (unsigned)hh) continue;
        #pragma unroll
        for (int dx = 0; dx < 3; dx++) {
            int xx = x + dx - 1;
            if ((unsigned)xx >= (unsigned)ww) continue;
            acc += v[(((long long)b * L + yy * ww + xx) << 8) + c] * lw[c * 9 + dy * 3 + dx];
        }
    }
    vs[idx] = v[idx] + acc;
}

// ---------------------------------------------------------------------------
// Attention (fp32 SIMT, validated round 1)
// ---------------------------------------------------------------------------
__global__ void __launch_bounds__(256) k_attn(const float* __restrict__ Pq,
                                              const float* __restrict__ Kmat,
                                              const float* __restrict__ Vmat,
                                              float* __restrict__ xbuf,
                                              int L, int branch) {
    __shared__ float qv[8 * 64];
    __shared__ float sc[8 * 1024];
    __shared__ float red[8 * 8];
    int qt = blockIdx.x, h = blockIdx.y, b = blockIdx.z;
    int tid = threadIdx.x;
    int q0 = qt * 8;
    int hglob = h + branch * NH2;

    for (int i = tid; i < 512; i += 256) {
        int qi = i >> 6, d = i & 63;
        qv[i] = Pq[(((size_t)(b * Qq + q0 + qi) * NH + hglob) << 6) + d] * 0.125f;
    }
    __syncthreads();

    float mx[8];
    #pragma unroll
    for (int qi = 0; qi < 8; qi++) mx[qi] = -1e30f;

    for (int l = tid; l < L; l += 256) {
        const float4* kp = (const float4*)(Kmat + (((size_t)b * L + l) << 8) + (h << 6));
        float acc[8] = {0, 0, 0, 0, 0, 0, 0, 0};
        #pragma unroll
        for (int c4 = 0; c4 < 16; c4++) {
            float4 kk = kp[c4];
            #pragma unroll
            for (int qi = 0; qi < 8; qi++) {
                const float* qq = &qv[(qi << 6) + (c4 << 2)];
                acc[qi] += kk.x * qq[0] + kk.y * qq[1] + kk.z * qq[2] + kk.w * qq[3];
            }
        }
        #pragma unroll
        for (int qi = 0; qi < 8; qi++) {
            sc[(qi << 10) + l] = acc[qi];
            mx[qi] = fmaxf(mx[qi], acc[qi]);
        }
    }

    int lane = tid & 31, w = tid >> 5;
    #pragma unroll
    for (int qi = 0; qi < 8; qi++) {
        float m = mx[qi];
        #pragma unroll
        for (int off = 16; off; off >>= 1) m = fmaxf(m, __shfl_xor_sync(0xffffffffu, m, off));
        mx[qi] = m;
    }
    if (lane == 0) {
        #pragma unroll
        for (int qi = 0; qi < 8; qi++) red[w * 8 + qi] = mx[qi];
    }
    __syncthreads();
    float bmax[8];
    #pragma unroll
    for (int qi = 0; qi < 8; qi++) {
        float m = red[qi];
        #pragma unroll
        for (int t = 1; t < 8; t++) m = fmaxf(m, red[t * 8 + qi]);
        bmax[qi] = m;
    }
    __syncthreads();

    float ls[8] = {0, 0, 0, 0, 0, 0, 0, 0};
    for (int l = tid; l < L; l += 256) {
        #pragma unroll
        for (int qi = 0; qi < 8; qi++) {
            float e = __expf(sc[(qi << 10) + l] - bmax[qi]);
            sc[(qi << 10) + l] = e;
            ls[qi] += e;
        }
    }
    #pragma unroll
    for (int qi = 0; qi < 8; qi++) {
        float v = ls[qi];
        #pragma unroll
        for (int off = 16; off; off >>= 1) v += __shfl_xor_sync(0xffffffffu, v, off);
        ls[qi] = v;
    }
    if (lane == 0) {
        #pragma unroll
        for (int qi = 0; qi < 8; qi++) red[w * 8 + qi] = ls[qi];
    }
    __syncthreads();
    float inv[8];
    #pragma unroll
    for (int qi = 0; qi < 8; qi++) {
        float s = 0.f;
        #pragma unroll
        for (int t = 0; t < 8; t++) s += red[t * 8 + qi];
        inv[qi] = 1.f / s;
    }
    __syncthreads();

    float acc2[8][8] = {};
    for (int l = lane; l < L; l += 32) {
        const float4* vp = (const float4*)(Vmat + (((size_t)b * L + l) << 8) + (h << 6) + (w << 3));
        float4 v0 = vp[0], v1 = vp[1];
        float pr[8];
        #pragma unroll
        for (int qi = 0; qi < 8; qi++) pr[qi] = sc[(qi << 10) + l];
        #pragma unroll
        for (int qi = 0; qi < 8; qi++) {
            acc2[qi][0] += pr[qi] * v0.x;
            acc2[qi][1] += pr[qi] * v0.y;
            acc2[qi][2] += pr[qi] * v0.z;
            acc2[qi][3] += pr[qi] * v0.w;
            acc2[qi][4] += pr[qi] * v1.x;
            acc2[qi][5] += pr[qi] * v1.y;
            acc2[qi][6] += pr[qi] * v1.z;
            acc2[qi][7] += pr[qi] * v1.w;
        }
    }
    #pragma unroll
    for (int qi = 0; qi < 8; qi++)
        #pragma unroll
        for (int j = 0; j < 8; j++) {
            float v = acc2[qi][j];
            #pragma unroll
            for (int off = 16; off; off >>= 1) v += __shfl_xor_sync(0xffffffffu, v, off);
            acc2[qi][j] = v;
        }
    if (lane == 0) {
        #pragma unroll
        for (int qi = 0; qi < 8; qi++)
            #pragma unroll
            for (int j = 0; j < 8; j++) {
                int d = (w << 3) + j;
                int f = (((b * Qq + q0 + qi) << 2) + h) * 64 + d;
                int q2 = f >> 11;
                int rem = f & 2047;
                int b2 = rem >> 8;
                int c2 = rem & 255;
                xbuf[((size_t)(q2 * Bn + b2)) * Dm + branch * C2 + c2] = acc2[qi][j] * inv[qi];
            }
    }
}

// ---------------------------------------------------------------------------
// host side
// ---------------------------------------------------------------------------
static void tc_gemm(int M, int N, int K,
                    const __nv_bfloat16* Ah0, const __nv_bfloat16* Al0,
                    const __nv_bfloat16* Bh0, const __nv_bfloat16* Bl0, float* C0,
                    const __nv_bfloat16* Ah1 = nullptr, const __nv_bfloat16* Al1 = nullptr,
                    const __nv_bfloat16* Bh1 = nullptr, const __nv_bfloat16* Bl1 = nullptr,
                    float* C1 = nullptr, const float* bias = nullptr) {
    GemmT g;
    g.Ah[0] = Ah0; g.Al[0] = Al0; g.Bh[0] = Bh0; g.Bl[0] = Bl0; g.C[0] = C0;
    g.Ah[1] = Ah1; g.Al[1] = Al1; g.Bh[1] = Bh1; g.Bl[1] = Bl1; g.C[1] = C1;
    g.bias = bias;
    int z = Ah1 ? 2 : 1;
    dim3 grid(N / 128, (M + 127) / 128, z);
    k_gemm<<<grid, 256, SMEM_BYTES>>>(M, N, K, g);
}

extern "C" void kernel_launch(void* const* d_in, const int* in_sizes, int n_in,
                              void* d_out, int out_size) {
    const float* query = (const float*)d_in[0];
    const float* key   = (const float*)d_in[1];
    const float* value = (const float*)d_in[2];
    const float* q_w   = (const float*)d_in[3];
    const float* sr11w = (const float*)d_in[4];
    const float* sr11b = (const float*)d_in[5];
    const float* n11g  = (const float*)d_in[6];
    const float* n11b  = (const float*)d_in[7];
    const float* sr12w = (const float*)d_in[8];
    const float* sr12b = (const float*)d_in[9];
    const float* n12g  = (const float*)d_in[10];
    const float* n12b  = (const float*)d_in[11];
    const float* sr21w = (const float*)d_in[12];
    const float* sr21b = (const float*)d_in[13];
    const float* n21g  = (const float*)d_in[14];
    const float* n21b  = (const float*)d_in[15];
    const float* sr22w = (const float*)d_in[16];
    const float* sr22b = (const float*)d_in[17];
    const float* n22g  = (const float*)d_in[18];
    const float* n22b  = (const float*)d_in[19];
    const float* k1w   = (const float*)d_in[20];
    const float* v1w   = (const float*)d_in[21];
    const float* k2w   = (const float*)d_in[22];
    const float* v2w   = (const float*)d_in[23];
    const float* lc1w  = (const float*)d_in[24];
    const float* lc1b  = (const float*)d_in[25];
    const float* lc2w  = (const float*)d_in[26];
    const float* lc2b  = (const float*)d_in[27];
    const float* projw = (const float*)d_in[28];
    const float* projb = (const float*)d_in[29];
    float* out = (float*)d_out;

    cudaFuncSetAttribute(k_gemm, cudaFuncAttributeMaxDynamicSharedMemorySize, SMEM_BYTES);

    __nv_bfloat16* bf;
    float* ff;
    cudaGetSymbolAddress((void**)&bf, g_bf);
    cudaGetSymbolAddress((void**)&ff, g_f);

    auto grd = [](long long total) { return (unsigned)((total + 255) / 256); };

    // --- weight prep ---
    k_cvt<<<grd(512 * 512), 256>>>(q_w,   bf + B_QWH, bf + B_QWL, 512 * 512);
    k_cvt<<<grd(512 * 512), 256>>>(projw, bf + B_PWH, bf + B_PWL, 512 * 512);
    k_cvt<<<grd(256 * 512), 256>>>(k1w, bf + B_KW1H, bf + B_KW1L, 256 * 512);
    k_cvt<<<grd(256 * 512), 256>>>(v1w, bf + B_VW1H, bf + B_VW1L, 256 * 512);
    k_cvt<<<grd(256 * 512), 256>>>(k2w, bf + B_KW2H, bf + B_KW2L, 256 * 512);
    k_cvt<<<grd(256 * 512), 256>>>(v2w, bf + B_VW2H, bf + B_VW2L, 256 * 512);
    k_twcv<<<grd((long long)512 * K1), 256>>>(sr11w, bf + B_W11H, bf + B_W11L, 16, 512, 512);
    k_twcv<<<grd((long long)512 * K1), 256>>>(sr12w, bf + B_W12H, bf + B_W12L, 16, 512, 512);
    k_twcv<<<grd((long long)512 * K2), 256>>>(sr21w, bf + B_W21H, bf + B_W21L, 4, 512, 512);
    k_twcv<<<grd((long long)512 * K2), 256>>>(sr22w, bf + B_W22H, bf + B_W22L, 4, 512, 512);

    // --- activation conversions + im2col ---
    k_cvt<<<grd((long long)MQ * 512), 256>>>(query, bf + B_QCH, bf + B_QCL, (long long)MQ * 512);
    k_im2col_bf<<<grd((long long)M1 * K1), 256>>>(key,   bf + B_A1KH, bf + B_A1KL, 16, 16, 4);
    k_im2col_bf<<<grd((long long)M1 * K1), 256>>>(value, bf + B_A1VH, bf + B_A1VL, 16, 16, 4);
    k_im2col_bf<<<grd((long long)M2 * K2), 256>>>(key,   bf + B_A2KH, bf + B_A2KL, 32, 32, 2);
    k_im2col_bf<<<grd((long long)M2 * K2), 256>>>(value, bf + B_A2VH, bf + B_A2VL, 32, 32, 2);

    // --- q projection ---
    tc_gemm(MQ, 512, 512, bf + B_QCH, bf + B_QCL, bf + B_QWH, bf + B_QWL, ff + F_PQ);

    // --- reduction convs as GEMMs ---
    tc_gemm(M1, 512, K1, bf + B_A1KH, bf + B_A1KL, bf + B_W11H, bf + B_W11L, ff + F_C1K,
            bf + B_A1VH, bf + B_A1VL, bf + B_W12H, bf + B_W12L, ff + F_C1V);
    tc_gemm(M2, 512, K2, bf + B_A2KH, bf + B_A2KL, bf + B_W21H, bf + B_W21L, ff + F_C2K,
            bf + B_A2VH, bf + B_A2VL, bf + B_W22H, bf + B_W22L, ff + F_C2V);

    // --- bias + LN + relu6 -> bf16 hi/lo ---
    k_biasln<<<M1, 256>>>(ff + F_C1K, sr11b, n11g, n11b, bf + B_K1CH, bf + B_K1CL);
    k_biasln<<<M1, 256>>>(ff + F_C1V, sr12b, n12g, n12b, bf + B_V1CH, bf + B_V1CL);
    k_biasln<<<M2, 256>>>(ff + F_C2K, sr21b, n21g, n21b, bf + B_K2CH, bf + B_K2CL);
    k_biasln<<<M2, 256>>>(ff + F_C2V, sr22b, n22g, n22b, bf + B_V2CH, bf + B_V2CL);

    // --- K/V head projections ---
    tc_gemm(M1, 256, 512, bf + B_K1CH, bf + B_K1CL, bf + B_KW1H, bf + B_KW1L, ff + F_KB1,
            bf + B_V1CH, bf + B_V1CL, bf + B_VW1H, bf + B_VW1L, ff + F_VB1);
    tc_gemm(M2, 256, 512, bf + B_K2CH, bf + B_K2CL, bf + B_KW2H, bf + B_KW2L, ff + F_KB2,
            bf + B_V2CH, bf + B_V2CL, bf + B_VW2H, bf + B_VW2L, ff + F_VB2);

    // --- depthwise local V + residual ---
    k_dwadd<<<grd((long long)M1 * 256), 256>>>(ff + F_VB1, ff + F_VS1, lc1w, lc1b, 16, 16);
    k_dwadd<<<grd((long long)M2 * 256), 256>>>(ff + F_VB2, ff + F_VS2, lc2w, lc2b, 32, 32);

    // --- attention branches ---
    k_attn<<<dim3(Qq / 8, NH2, Bn), 256>>>(ff + F_PQ, ff + F_KB1, ff + F_VS1, ff + F_X, L1, 0);
    k_attn<<<dim3(Qq / 8, NH2, Bn), 256>>>(ff + F_PQ, ff + F_KB2, ff + F_VS2, ff + F_X, L2, 1);

    // --- final projection (+bias) ---
    k_cvt<<<grd((long long)MQ * 512), 256>>>(ff + F_X, bf + B_XCH, bf + B_XCL, (long long)MQ * 512);
    tc_gemm(MQ, 512, 512, bf + B_XCH, bf + B_XCL, bf + B_PWH, bf + B_PWL, out,
            nullptr, nullptr, nullptr, nullptr, nullptr, projb);

    (void)in_sizes; (void)n_in; (void)out_size;
}

// round 4
// speedup vs baseline: 2.6292x; 2.0033x over previous
#include <cuda_runtime.h>
#include <cuda_bf16.h>
#include <cstdint>
#include <cstddef>

// ---------------------------------------------------------------------------
// Problem constants
// ---------------------------------------------------------------------------
#define Dm    512
#define Bn    8
#define Hh    64
#define Ww    64
#define Nn    (Hh*Ww)      // 4096
#define Qq    200
#define C2    256
#define NH    8
#define NH2   4
#define HD    64
#define L1    256
#define L2    1024
#define M1    (Bn*L1)      // 2048
#define M2    (Bn*L2)      // 8192
#define K1    (Dm*16)      // 8192
#define K2    (Dm*4)       // 2048
#define MQ    (Qq*Bn)      // 1600

// ---------------------------------------------------------------------------
// fp32 scratch pool
// ---------------------------------------------------------------------------
constexpr size_t S_W11T = 0;
constexpr size_t S_W12T = S_W11T + 512u*8192u;
constexpr size_t S_W21T = S_W12T + 512u*8192u;
constexpr size_t S_W22T = S_W21T + 512u*2048u;
constexpr size_t S_QWR  = S_W22T + 512u*2048u;
constexpr size_t S_PWR  = S_QWR  + 512u*512u;
constexpr size_t S_KW1R = S_PWR  + 512u*512u;
constexpr size_t S_VW1R = S_KW1R + 256u*512u;
constexpr size_t S_KW2R = S_VW1R + 256u*512u;
constexpr size_t S_VW2R = S_KW2R + 256u*512u;
constexpr size_t S_QR   = S_VW2R + 256u*512u;
constexpr size_t S_KEYR = S_QR   + (size_t)MQ*512u;
constexpr size_t S_VALR = S_KEYR + (size_t)Bn*Nn*512u;
constexpr size_t S_PQ   = S_VALR + (size_t)Bn*Nn*512u;
constexpr size_t S_C1K  = S_PQ   + (size_t)MQ*512u;
constexpr size_t S_C1V  = S_C1K  + (size_t)M1*512u;
constexpr size_t S_C2K  = S_C1V  + (size_t)M1*512u;
constexpr size_t S_C2V  = S_C2K  + (size_t)M2*512u;
constexpr size_t S_LN1K = S_C2V  + (size_t)M2*512u;
constexpr size_t S_LN1V = S_LN1K + (size_t)M1*512u;
constexpr size_t S_LN2K = S_LN1V + (size_t)M1*512u;
constexpr size_t S_LN2V = S_LN2K + (size_t)M2*512u;
constexpr size_t S_KB1  = S_LN2V + (size_t)M2*512u;
constexpr size_t S_VB1  = S_KB1  + (size_t)M1*256u;
constexpr size_t S_KB2  = S_VB1  + (size_t)M1*256u;
constexpr size_t S_VB2  = S_KB2  + (size_t)M2*256u;
constexpr size_t S_VS1  = S_VB2  + (size_t)M2*256u;
constexpr size_t S_VS2  = S_VS1  + (size_t)M1*256u;
constexpr size_t S_X    = S_VS2  + (size_t)M2*256u;
constexpr size_t S_TOTAL = S_X   + (size_t)MQ*512u;

__device__ __align__(16) float g_f[S_TOTAL];

// ---------------------------------------------------------------------------
// helpers
// ---------------------------------------------------------------------------
__device__ __forceinline__ uint32_t smem_u32(const void* p) {
    uint32_t a;
    asm("{ .reg .u64 t; cvta.to.shared.u64 t, %1; cvt.u32.u64 %0, t; }" : "=r"(a) : "l"(p));
    return a;
}
__device__ __forceinline__ float tf32r(float x) {
    float y;
    asm("cvt.rna.tf32.f32 %0, %1;" : "=f"(y) : "f"(x));
    return y;
}

#define MMA_TF32(c, a, b) \
    asm volatile("mma.sync.aligned.m16n8k8.row.col.f32.tf32.tf32.f32 " \
        "{%0,%1,%2,%3}, {%4,%5,%6,%7}, {%8,%9}, {%0,%1,%2,%3};" \
        : "+f"((c)[0]), "+f"((c)[1]), "+f"((c)[2]), "+f"((c)[3]) \
        : "r"((a)[0]), "r"((a)[1]), "r"((a)[2]), "r"((a)[3]), \
          "r"((b)[0]), "r"((b)[1]))

// ---------------------------------------------------------------------------
// prep: all weights in one kernel.  seg P==1: copy+round.  P>1: conv
// transpose [Cout][512][P] -> [Cout][p*512+ci] + round.
// ---------------------------------------------------------------------------
struct PrepW {
    const float* src[10];
    float* dst[10];
    int P[10];
    long long n[10];
};
__global__ void k_prep_w(PrepW pw) {
    int seg = blockIdx.y;
    long long idx = (long long)blockIdx.x * 256 + threadIdx.x;
    if (idx >= pw.n[seg]) return;
    const float* s = pw.src[seg];
    int P = pw.P[seg];
    float v;
    if (P == 1) {
        v = s[idx];
    } else {
        int ci = (int)(idx & 511);
        long long t = idx >> 9;
        int p = (int)(t % P);
        int co = (int)(t / P);
        v = s[((long long)co * 512 + ci) * P + p];
    }
    pw.dst[seg][idx] = tf32r(v);
}

// prep: query/key/value rounding (float4-vectorized), 3 segments
struct PrepA {
    const float* src[3];
    float* dst[3];
    long long n4[3];
};
__global__ void k_prep_a(PrepA pa) {
    int seg = blockIdx.y;
    long long i = (long long)blockIdx.x * 256 + threadIdx.x;
    if (i >= pa.n4[seg]) return;
    float4 v = ((const float4*)pa.src[seg])[i];
    v.x = tf32r(v.x); v.y = tf32r(v.y); v.z = tf32r(v.z); v.w = tf32r(v.w);
    ((float4*)pa.dst[seg])[i] = v;
}

// ---------------------------------------------------------------------------
// TF32 GEMM: C[M,N] = A[M,K] @ Bt[N,K]^T (+bias)
// 128x128 CTA tile, BK=32, double-buffered cp.async, 8 warps (64x32 each).
// mode 0: plain A.  mode 1/2: fused im2col of (B,4096,512) tensor, KS=4/2.
// blockIdx.z picks one of up to 2 sub-problems.
// ---------------------------------------------------------------------------
struct GemmP {
    const float* A[2];
    const float* B[2];
    float* C[2];
    const float* bias;
    int mode;
};

#define PITCH 36                      // floats per smem row
#define STAGEF (2 * 128 * PITCH)      // floats per stage (A+B planes) = 9216
#define GSMEM_BYTES (2 * STAGEF * 4)  // 73728

__global__ void __launch_bounds__(256) k_gemm(int M, int N, int K, GemmP g) {
    extern __shared__ float sm[];
    int z = blockIdx.z;
    const float* A = g.A[z];
    const float* B = g.B[z];
    float* C = g.C[z];
    int mode = g.mode;
    int rowBase = blockIdx.y * 128;
    int colBase = blockIdx.x * 128;
    int tid = threadIdx.x, wid = tid >> 5, lane = tid & 31;
    int wm = wid & 1, wn = wid >> 1;
    uint32_t sb = smem_u32(sm);

    auto issue = [&](int stage, int kb) {
        uint32_t sbase = sb + stage * (STAGEF * 4);
        // A plane
        #pragma unroll
        for (int t = 0; t < 4; t++) {
            int cid = tid + t * 256;
            int r = cid >> 3, ch = cid & 7;
            int grow = rowBase + r;
            const float* src;
            int sz = 16;
            if (mode == 0) {
                if (grow >= M) { sz = 0; grow = 0; }
                src = A + (size_t)grow * K + kb + ch * 4;
            } else if (mode == 1) {
                int b = grow >> 8, rem = grow & 255;
                int oy = rem >> 4, ox = rem & 15;
                int p = kb >> 9;
                int y = oy * 4 + (p >> 2), x = ox * 4 + (p & 3);
                src = A + (((size_t)((b << 12) + (y << 6) + x)) << 9) + (kb & 511) + ch * 4;
            } else {
                int b = grow >> 10, oy = (grow >> 5) & 31, ox = grow & 31;
                int p = kb >> 9;
                int y = oy * 2 + (p >> 1), x = ox * 2 + (p & 1);
                src = A + (((size_t)((b << 12) + (y << 6) + x)) << 9) + (kb & 511) + ch * 4;
            }
            uint32_t sa = sbase + (uint32_t)(r * PITCH) * 4 + ch * 16;
            asm volatile("cp.async.cg.shared.global [%0], [%1], 16, %2;"
                         :: "r"(sa), "l"(src), "r"(sz) : "memory");
        }
        // B plane
        #pragma unroll
        for (int t = 0; t < 4; t++) {
            int cid = tid + t * 256;
            int r = cid >> 3, ch = cid & 7;
            const float* src = B + (size_t)(colBase + r) * K + kb + ch * 4;
            uint32_t sa = sbase + (uint32_t)((128 + r) * PITCH) * 4 + ch * 16;
            asm volatile("cp.async.cg.shared.global [%0], [%1], 16, 16;"
                         :: "r"(sa), "l"(src) : "memory");
        }
        asm volatile("cp.async.commit_group;" ::: "memory");
    };

    float acc[4][4][4];
    #pragma unroll
    for (int a = 0; a < 4; a++)
        #pragma unroll
        for (int b = 0; b < 4; b++)
            #pragma unroll
            for (int c = 0; c < 4; c++) acc[a][b][c] = 0.f;

    int niter = K >> 5;
    issue(0, 0);
    int r4 = lane >> 2, c4 = lane & 3;

    for (int it = 0; it < niter; it++) {
        if (it + 1 < niter) {
            issue((it + 1) & 1, (it + 1) << 5);
            asm volatile("cp.async.wait_group 1;" ::: "memory");
        } else {
            asm volatile("cp.async.wait_group 0;" ::: "memory");
        }
        __syncthreads();
        const float* sA = sm + (it & 1) * STAGEF;
        const float* sB = sA + 128 * PITCH;

        #pragma unroll
        for (int kk = 0; kk < 32; kk += 8) {
            uint32_t af[4][4], bf_[4][2];
            #pragma unroll
            for (int mt = 0; mt < 4; mt++) {
                int row = wm * 64 + mt * 16 + r4;
                af[mt][0] = *(const uint32_t*)&sA[row * PITCH + kk + c4];
                af[mt][1] = *(const uint32_t*)&sA[(row + 8) * PITCH + kk + c4];
                af[mt][2] = *(const uint32_t*)&sA[row * PITCH + kk + c4 + 4];
                af[mt][3] = *(const uint32_t*)&sA[(row + 8) * PITCH + kk + c4 + 4];
            }
            #pragma unroll
            for (int nt = 0; nt < 4; nt++) {
                int n = wn * 32 + nt * 8 + r4;
                bf_[nt][0] = *(const uint32_t*)&sB[n * PITCH + kk + c4];
                bf_[nt][1] = *(const uint32_t*)&sB[n * PITCH + kk + c4 + 4];
            }
            #pragma unroll
            for (int mt = 0; mt < 4; mt++)
                #pragma unroll
                for (int nt = 0; nt < 4; nt++)
                    MMA_TF32(acc[mt][nt], af[mt], bf_[nt]);
        }
        __syncthreads();
    }

    const float* bias = g.bias;
    #pragma unroll
    for (int mt = 0; mt < 4; mt++) {
        #pragma unroll
        for (int nt = 0; nt < 4; nt++) {
            int m0 = rowBase + wm * 64 + mt * 16 + r4;
            int n0 = colBase + wn * 32 + nt * 8 + 2 * c4;
            float bx = 0.f, by = 0.f;
            if (bias) { bx = bias[n0]; by = bias[n0 + 1]; }
            if (m0 < M) {
                float2 v = make_float2(acc[mt][nt][0] + bx, acc[mt][nt][1] + by);
                *(float2*)(C + (size_t)m0 * N + n0) = v;
            }
            if (m0 + 8 < M) {
                float2 v = make_float2(acc[mt][nt][2] + bx, acc[mt][nt][3] + by);
                *(float2*)(C + (size_t)(m0 + 8) * N + n0) = v;
            }
        }
    }
}

// ---------------------------------------------------------------------------
// bias + LayerNorm(512) + relu6 -> tf32-rounded fp32.  grid (rows, 2).
// ---------------------------------------------------------------------------
struct LnP {
    const float* x[2];
    const float* cb[2];
    const float* g[2];
    const float* b[2];
    float* o[2];
};
__device__ __forceinline__ float blockReduceSum256(float v, float* sbuf) {
    int lane = threadIdx.x & 31, w = threadIdx.x >> 5;
    #pragma unroll
    for (int off = 16; off; off >>= 1) v += __shfl_xor_sync(0xffffffffu, v, off);
    if (lane == 0) sbuf[w] = v;
    __syncthreads();
    float s = 0.f;
    #pragma unroll
    for (int t = 0; t < 8; t++) s += sbuf[t];
    __syncthreads();
    return s;
}

__global__ void __launch_bounds__(256) k_biasln(LnP p) {
    __shared__ float sbuf[8];
    int row = blockIdx.x, tid = threadIdx.x, zz = blockIdx.y;
    const float* xr = p.x[zz] + (size_t)row * 512;
    const float* cb = p.cb[zz];
    const float* gg = p.g[zz];
    const float* bb = p.b[zz];
    float* orow = p.o[zz] + (size_t)row * 512;
    float v0 = xr[tid] + cb[tid];
    float v1 = xr[tid + 256] + cb[tid + 256];
    float s = blockReduceSum256(v0 + v1, sbuf);
    float mean = s * (1.f / 512.f);
    float d0 = v0 - mean, d1 = v1 - mean;
    float s2 = blockReduceSum256(d0 * d0 + d1 * d1, sbuf);
    float inv = rsqrtf(s2 * (1.f / 512.f) + 1e-5f);
    float y0 = d0 * inv * gg[tid] + bb[tid];
    float y1 = d1 * inv * gg[tid + 256] + bb[tid + 256];
    y0 = fminf(fmaxf(y0, 0.f), 6.f);
    y1 = fminf(fmaxf(y1, 0.f), 6.f);
    orow[tid]       = tf32r(y0);
    orow[tid + 256] = tf32r(y1);
}

// ---------------------------------------------------------------------------
// depthwise 3x3 (pad 1) + bias + residual add
// ---------------------------------------------------------------------------
__global__ void k_dwadd(const float* __restrict__ v, float* __restrict__ vs,
                        const float* __restrict__ lw, const float* __restrict__ lb,
                        int hh, int ww) {
    int L = hh * ww;
    long long idx = (long long)blockIdx.x * 256 + threadIdx.x;
    long long total = (long long)Bn * L * C2;
    if (idx >= total) return;
    int c = (int)(idx & 255);
    int l = (int)((idx >> 8) % L);
    int b = (int)(idx / ((long long)L << 8));
    int y = l / ww, x = l % ww;
    float acc = lb[c];
    #pragma unroll
    for (int dy = 0; dy < 3; dy++) {
        int yy = y + dy - 1;
        if ((unsigned)yy >= (unsigned)hh) continue;
        #pragma unroll
        for (int dx = 0; dx < 3; dx++) {
            int xx = x + dx - 1;
            if ((unsigned)xx >= (unsigned)ww) continue;
            acc += v[(((long long)b * L + yy * ww + xx) << 8) + c] * lw[c * 9 + dy * 3 + dx];
        }
    }
    vs[idx] = v[idx] + acc;
}

// ---------------------------------------------------------------------------
// Attention (fp32 SIMT, validated) — output tf32-rounded for final GEMM
// ---------------------------------------------------------------------------
__global__ void __launch_bounds__(256) k_attn(const float* __restrict__ Pq,
                                              const float* __restrict__ Kmat,
                                              const float* __restrict__ Vmat,
                                              float* __restrict__ xbuf,
                                              int L, int branch) {
    __shared__ float qv[8 * 64];
    __shared__ float sc[8 * 1024];
    __shared__ float red[8 * 8];
    int qt = blockIdx.x, h = blockIdx.y, b = blockIdx.z;
    int tid = threadIdx.x;
    int q0 = qt * 8;
    int hglob = h + branch * NH2;

    for (int i = tid; i < 512; i += 256) {
        int qi = i >> 6, d = i & 63;
        qv[i] = Pq[(((size_t)(b * Qq + q0 + qi) * NH + hglob) << 6) + d] * 0.125f;
    }
    __syncthreads();

    float mx[8];
    #pragma unroll
    for (int qi = 0; qi < 8; qi++) mx[qi] = -1e30f;

    for (int l = tid; l < L; l += 256) {
        const float4* kp = (const float4*)(Kmat + (((size_t)b * L + l) << 8) + (h << 6));
        float acc[8] = {0, 0, 0, 0, 0, 0, 0, 0};
        #pragma unroll
        for (int c4i = 0; c4i < 16; c4i++) {
            float4 kk = kp[c4i];
            #pragma unroll
            for (int qi = 0; qi < 8; qi++) {
                const float* qq = &qv[(qi << 6) + (c4i << 2)];
                acc[qi] += kk.x * qq[0] + kk.y * qq[1] + kk.z * qq[2] + kk.w * qq[3];
            }
        }
        #pragma unroll
        for (int qi = 0; qi < 8; qi++) {
            sc[(qi << 10) + l] = acc[qi];
            mx[qi] = fmaxf(mx[qi], acc[qi]);
        }
    }

    int lane = tid & 31, w = tid >> 5;
    #pragma unroll
    for (int qi = 0; qi < 8; qi++) {
        float m = mx[qi];
        #pragma unroll
        for (int off = 16; off; off >>= 1) m = fmaxf(m, __shfl_xor_sync(0xffffffffu, m, off));
        mx[qi] = m;
    }
    if (lane == 0) {
        #pragma unroll
        for (int qi = 0; qi < 8; qi++) red[w * 8 + qi] = mx[qi];
    }
    __syncthreads();
    float bmax[8];
    #pragma unroll
    for (int qi = 0; qi < 8; qi++) {
        float m = red[qi];
        #pragma unroll
        for (int t = 1; t < 8; t++) m = fmaxf(m, red[t * 8 + qi]);
        bmax[qi] = m;
    }
    __syncthreads();

    float ls[8] = {0, 0, 0, 0, 0, 0, 0, 0};
    for (int l = tid; l < L; l += 256) {
        #pragma unroll
        for (int qi = 0; qi < 8; qi++) {
            float e = __expf(sc[(qi << 10) + l] - bmax[qi]);
            sc[(qi << 10) + l] = e;
            ls[qi] += e;
        }
    }
    #pragma unroll
    for (int qi = 0; qi < 8; qi++) {
        float v = ls[qi];
        #pragma unroll
        for (int off = 16; off; off >>= 1) v += __shfl_xor_sync(0xffffffffu, v, off);
        ls[qi] = v;
    }
    if (lane == 0) {
        #pragma unroll
        for (int qi = 0; qi < 8; qi++) red[w * 8 + qi] = ls[qi];
    }
    __syncthreads();
    float inv[8];
    #pragma unroll
    for (int qi = 0; qi < 8; qi++) {
        float s = 0.f;
        #pragma unroll
        for (int t = 0; t < 8; t++) s += red[t * 8 + qi];
        inv[qi] = 1.f / s;
    }
    __syncthreads();

    float acc2[8][8] = {};
    for (int l = lane; l < L; l += 32) {
        const float4* vp = (const float4*)(Vmat + (((size_t)b * L + l) << 8) + (h << 6) + (w << 3));
        float4 v0 = vp[0], v1 = vp[1];
        float pr[8];
        #pragma unroll
        for (int qi = 0; qi < 8; qi++) pr[qi] = sc[(qi << 10) + l];
        #pragma unroll
        for (int qi = 0; qi < 8; qi++) {
            acc2[qi][0] += pr[qi] * v0.x;
            acc2[qi][1] += pr[qi] * v0.y;
            acc2[qi][2] += pr[qi] * v0.z;
            acc2[qi][3] += pr[qi] * v0.w;
            acc2[qi][4] += pr[qi] * v1.x;
            acc2[qi][5] += pr[qi] * v1.y;
            acc2[qi][6] += pr[qi] * v1.z;
            acc2[qi][7] += pr[qi] * v1.w;
        }
    }
    #pragma unroll
    for (int qi = 0; qi < 8; qi++)
        #pragma unroll
        for (int j = 0; j < 8; j++) {
            float v = acc2[qi][j];
            #pragma unroll
            for (int off = 16; off; off >>= 1) v += __shfl_xor_sync(0xffffffffu, v, off);
            acc2[qi][j] = v;
        }
    if (lane == 0) {
        #pragma unroll
        for (int qi = 0; qi < 8; qi++)
            #pragma unroll
            for (int j = 0; j < 8; j++) {
                int d = (w << 3) + j;
                int f = (((b * Qq + q0 + qi) << 2) + h) * 64 + d;
                int q2 = f >> 11;
                int rem = f & 2047;
                int b2 = rem >> 8;
                int c2 = rem & 255;
                xbuf[((size_t)(q2 * Bn + b2)) * Dm + branch * C2 + c2] = tf32r(acc2[qi][j] * inv[qi]);
            }
    }
}

// ---------------------------------------------------------------------------
// host side
// ---------------------------------------------------------------------------
static void gemm(int M, int N, int K, int mode,
                 const float* A0, const float* B0, float* C0,
                 const float* A1 = nullptr, const float* B1 = nullptr,
                 float* C1 = nullptr, const float* bias = nullptr) {
    GemmP g;
    g.A[0] = A0; g.A[1] = A1;
    g.B[0] = B0; g.B[1] = B1;
    g.C[0] = C0; g.C[1] = C1;
    g.bias = bias;
    g.mode = mode;
    int z = A1 ? 2 : 1;
    dim3 grid(N / 128, (M + 127) / 128, z);
    k_gemm<<<grid, 256, GSMEM_BYTES>>>(M, N, K, g);
}

extern "C" void kernel_launch(void* const* d_in, const int* in_sizes, int n_in,
                              void* d_out, int out_size) {
    const float* query = (const float*)d_in[0];
    const float* key   = (const float*)d_in[1];
    const float* value = (const float*)d_in[2];
    const float* q_w   = (const float*)d_in[3];
    const float* sr11w = (const float*)d_in[4];
    const float* sr11b = (const float*)d_in[5];
    const float* n11g  = (const float*)d_in[6];
    const float* n11b  = (const float*)d_in[7];
    const float* sr12w = (const float*)d_in[8];
    const float* sr12b = (const float*)d_in[9];
    const float* n12g  = (const float*)d_in[10];
    const float* n12b  = (const float*)d_in[11];
    const float* sr21w = (const float*)d_in[12];
    const float* sr21b = (const float*)d_in[13];
    const float* n21g  = (const float*)d_in[14];
    const float* n21b  = (const float*)d_in[15];
    const float* sr22w = (const float*)d_in[16];
    const float* sr22b = (const float*)d_in[17];
    const float* n22g  = (const float*)d_in[18];
    const float* n22b  = (const float*)d_in[19];
    const float* k1w   = (const float*)d_in[20];
    const float* v1w   = (const float*)d_in[21];
    const float* k2w   = (const float*)d_in[22];
    const float* v2w   = (const float*)d_in[23];
    const float* lc1w  = (const float*)d_in[24];
    const float* lc1b  = (const float*)d_in[25];
    const float* lc2w  = (const float*)d_in[26];
    const float* lc2b  = (const float*)d_in[27];
    const float* projw = (const float*)d_in[28];
    const float* projb = (const float*)d_in[29];
    float* out = (float*)d_out;

    cudaFuncSetAttribute(k_gemm, cudaFuncAttributeMaxDynamicSharedMemorySize, GSMEM_BYTES);

    float* ff;
    cudaGetSymbolAddress((void**)&ff, g_f);

    auto grd = [](long long total) { return (unsigned)((total + 255) / 256); };

    // 1. weight prep (all in one launch)
    {
        PrepW pw;
        pw.src[0] = sr11w; pw.dst[0] = ff + S_W11T; pw.P[0] = 16; pw.n[0] = (long long)512 * K1;
        pw.src[1] = sr12w; pw.dst[1] = ff + S_W12T; pw.P[1] = 16; pw.n[1] = (long long)512 * K1;
        pw.src[2] = sr21w; pw.dst[2] = ff + S_W21T; pw.P[2] = 4;  pw.n[2] = (long long)512 * K2;
        pw.src[3] = sr22w; pw.dst[3] = ff + S_W22T; pw.P[3] = 4;  pw.n[3] = (long long)512 * K2;
        pw.src[4] = q_w;   pw.dst[4] = ff + S_QWR;  pw.P[4] = 1;  pw.n[4] = 512 * 512;
        pw.src[5] = projw; pw.dst[5] = ff + S_PWR;  pw.P[5] = 1;  pw.n[5] = 512 * 512;
        pw.src[6] = k1w;   pw.dst[6] = ff + S_KW1R; pw.P[6] = 1;  pw.n[6] = 256 * 512;
        pw.src[7] = v1w;   pw.dst[7] = ff + S_VW1R; pw.P[7] = 1;  pw.n[7] = 256 * 512;
        pw.src[8] = k2w;   pw.dst[8] = ff + S_KW2R; pw.P[8] = 1;  pw.n[8] = 256 * 512;
        pw.src[9] = v2w;   pw.dst[9] = ff + S_VW2R; pw.P[9] = 1;  pw.n[9] = 256 * 512;
        dim3 gw(grd((long long)512 * K1), 10);
        k_prep_w<<<gw, 256>>>(pw);
    }
    // 2. activation rounding (query/key/value)
    {
        PrepA pa;
        pa.src[0] = query; pa.dst[0] = ff + S_QR;   pa.n4[0] = (long long)MQ * 512 / 4;
        pa.src[1] = key;   pa.dst[1] = ff + S_KEYR; pa.n4[1] = (long long)Bn * Nn * 512 / 4;
        pa.src[2] = value; pa.dst[2] = ff + S_VALR; pa.n4[2] = (long long)Bn * Nn * 512 / 4;
        dim3 ga(grd((long long)Bn * Nn * 512 / 4), 3);
        k_prep_a<<<ga, 256>>>(pa);
    }
    // 3. q projection
    gemm(MQ, 512, 512, 0, ff + S_QR, ff + S_QWR, ff + S_PQ);
    // 4. conv1 (fused im2col, z=2)
    gemm(M1, 512, K1, 1, ff + S_KEYR, ff + S_W11T, ff + S_C1K,
         ff + S_VALR, ff + S_W12T, ff + S_C1V);
    // 5. branch-1 LN (k+v fused in grid.y)
    {
        LnP p;
        p.x[0] = ff + S_C1K; p.cb[0] = sr11b; p.g[0] = n11g; p.b[0] = n11b; p.o[0] = ff + S_LN1K;
        p.x[1] = ff + S_C1V; p.cb[1] = sr12b; p.g[1] = n12g; p.b[1] = n12b; p.o[1] = ff + S_LN1V;
        k_biasln<<<dim3(M1, 2), 256>>>(p);
    }
    // 6. conv2 (fused im2col, z=2)  <-- ncu profiled launch
    gemm(M2, 512, K2, 2, ff + S_KEYR, ff + S_W21T, ff + S_C2K,
         ff + S_VALR, ff + S_W22T, ff + S_C2V);
    // 7. branch-2 LN
    {
        LnP p;
        p.x[0] = ff + S_C2K; p.cb[0] = sr21b; p.g[0] = n21g; p.b[0] = n21b; p.o[0] = ff + S_LN2K;
        p.x[1] = ff + S_C2V; p.cb[1] = sr22b; p.g[1] = n22g; p.b[1] = n22b; p.o[1] = ff + S_LN2V;
        k_biasln<<<dim3(M2, 2), 256>>>(p);
    }
    // 8-9. K/V head projections
    gemm(M1, 256, 512, 0, ff + S_LN1K, ff + S_KW1R, ff + S_KB1,
         ff + S_LN1V, ff + S_VW1R, ff + S_VB1);
    gemm(M2, 256, 512, 0, ff + S_LN2K, ff + S_KW2R, ff + S_KB2,
         ff + S_LN2V, ff + S_VW2R, ff + S_VB2);
    // 10-11. depthwise local V + residual
    k_dwadd<<<grd((long long)M1 * 256), 256>>>(ff + S_VB1, ff + S_VS1, lc1w, lc1b, 16, 16);
    k_dwadd<<<grd((long long)M2 * 256), 256>>>(ff + S_VB2, ff + S_VS2, lc2w, lc2b, 32, 32);
    // 12-13. attention
    k_attn<<<dim3(Qq / 8, NH2, Bn), 256>>>(ff + S_PQ, ff + S_KB1, ff + S_VS1, ff + S_X, L1, 0);
    k_attn<<<dim3(Qq / 8, NH2, Bn), 256>>>(ff + S_PQ, ff + S_KB2, ff + S_VS2, ff + S_X, L2, 1);
    // 14. final projection (+bias)
    gemm(MQ, 512, 512, 0, ff + S_X, ff + S_PWR, out,
         nullptr, nullptr, nullptr, projb);

    (void)in_sizes; (void)n_in; (void)out_size;
}